// round 15
// baseline (speedup 1.0000x reference)
#include <cuda_runtime.h>
#include <cuda_fp16.h>
#include <math.h>

#define TT 2048
#define CC 1024
#define HH 16
#define DD 64
#define EE 8
#define FF 4096

// ------------------------- scratch (device globals; no allocs) ---------------
__device__ float g_xn  [TT * CC];          // LN1 output
__device__ float g_q   [HH * TT * DD];     // (H,T,D) fp32, PRE-ROUNDED to tf32
__device__ float g_k   [HH * TT * DD];
__device__ float g_v   [HH * TT * DD];
__device__ float g_att [TT * CC];          // concat-head attention output
__device__ float g_xn2 [TT * CC];          // LN2 output
__device__ __half g_Hbuf[(size_t)TT * 2 * FF]; // expert hidden (fp16), slot-indexed
__device__ float g_O2  [(size_t)TT * 2 * CC];  // expert output * gate, slot-indexed
__device__ float g_gate[TT * 2];
__device__ int   g_list[EE * TT];
__device__ int   g_count[EE];

// fp16 transposed expert weights: stored [n][k] (k contiguous)
__device__ __half h_W1[(size_t)EE * FF * CC]; // per e: [n=F][k=C]
__device__ __half h_W2[(size_t)EE * CC * FF]; // per e: [n=C][k=F]

// ------------------------------ helpers --------------------------------------
__device__ __forceinline__ float to_tf32(float x) {
    float r;
    asm("cvt.rna.tf32.f32 %0, %1;" : "=f"(r) : "f"(x));
    return r;
}

__device__ __forceinline__ void mma_tf32(float* c, const unsigned* a, const unsigned* b) {
    asm volatile(
        "mma.sync.aligned.m16n8k8.row.col.f32.tf32.tf32.f32 "
        "{%0,%1,%2,%3}, {%4,%5,%6,%7}, {%8,%9}, {%0,%1,%2,%3};"
        : "+f"(c[0]), "+f"(c[1]), "+f"(c[2]), "+f"(c[3])
        : "r"(a[0]), "r"(a[1]), "r"(a[2]), "r"(a[3]), "r"(b[0]), "r"(b[1]));
}

__device__ __forceinline__ void mma_f16(float* c, const unsigned* a,
                                        unsigned b0, unsigned b1) {
    asm volatile(
        "mma.sync.aligned.m16n8k16.row.col.f32.f16.f16.f32 "
        "{%0,%1,%2,%3}, {%4,%5,%6,%7}, {%8,%9}, {%0,%1,%2,%3};"
        : "+f"(c[0]), "+f"(c[1]), "+f"(c[2]), "+f"(c[3])
        : "r"(a[0]), "r"(a[1]), "r"(a[2]), "r"(a[3]), "r"(b0), "r"(b1));
}

__device__ __forceinline__ unsigned packh2(float x, float y) {
    __half2 h = __floats2half2_rn(x, y);
    return *(unsigned*)&h;
}

// XOR swizzle for 64-float rows (float4-safe: XOR touches bits >= 2 only)
#define SWZF(r, c) ((c) ^ (((r) & 15) << 2))

__device__ __forceinline__ unsigned smem_u32(const void* p) {
    return (unsigned)__cvta_generic_to_shared(p);
}
__device__ __forceinline__ void cp_async16(unsigned dst, const void* src) {
    asm volatile("cp.async.ca.shared.global [%0], [%1], 16;" :: "r"(dst), "l"(src));
}
__device__ __forceinline__ void cp_commit() {
    asm volatile("cp.async.commit_group;" ::: "memory");
}
__device__ __forceinline__ void cp_wait_all() {
    asm volatile("cp.async.wait_group 0;" ::: "memory");
}

// --------------------- weight transpose+convert (fp32 -> fp16 [n][k]) --------
__global__ void transpose_h_kernel(const float* __restrict__ src,
                                   __half* __restrict__ dst,
                                   int rows, int cols,
                                   size_t sstride, size_t dstride)
{
    __shared__ __half tile[32][33];
    const size_t b = blockIdx.z;
    const int c0 = blockIdx.x * 32, r0 = blockIdx.y * 32;
    const int tx = threadIdx.x, ty = threadIdx.y;
#pragma unroll
    for (int i = 0; i < 4; i++) {
        int r = r0 + ty + i * 8;
        tile[ty + i * 8][tx] =
            __float2half(src[b * sstride + (size_t)r * cols + c0 + tx]);
    }
    __syncthreads();
#pragma unroll
    for (int i = 0; i < 4; i++) {
        int c = c0 + ty + i * 8;
        dst[b * dstride + (size_t)c * rows + r0 + tx] = tile[tx][ty + i * 8];
    }
}

// ------------------------------ LayerNorm ------------------------------------
template <int PHASE>
__global__ void ln_kernel(const float* __restrict__ x,
                          const float* __restrict__ gamma,
                          const float* __restrict__ beta)
{
    int t = blockIdx.x;
    const float* xr = x + (size_t)t * CC;
    float s = 0.f, s2 = 0.f;
    for (int c = threadIdx.x; c < CC; c += 256) {
        float v = xr[c]; s += v; s2 += v * v;
    }
#pragma unroll
    for (int o = 16; o > 0; o >>= 1) {
        s  += __shfl_xor_sync(0xffffffffu, s,  o);
        s2 += __shfl_xor_sync(0xffffffffu, s2, o);
    }
    __shared__ float sm[8], sm2[8];
    __shared__ float smean, srstd;
    if ((threadIdx.x & 31) == 0) { sm[threadIdx.x >> 5] = s; sm2[threadIdx.x >> 5] = s2; }
    __syncthreads();
    if (threadIdx.x == 0) {
        float a = 0.f, a2 = 0.f;
        for (int i = 0; i < 8; i++) { a += sm[i]; a2 += sm2[i]; }
        float m   = a * (1.f / CC);
        float var = a2 * (1.f / CC) - m * m;
        smean = m; srstd = rsqrtf(var + 1e-5f);
    }
    __syncthreads();
    float m = smean, r = srstd;
    float* out = (PHASE == 0) ? g_xn : g_xn2;
    for (int c = threadIdx.x; c < CC; c += 256)
        out[(size_t)t * CC + c] = (xr[c] - m) * r * gamma[c] + beta[c];
}

// ------------------------- tf32 GEMM (router-upstream path) ------------------
// MODE 0: QKV fused  (out pre-rounded to tf32)   MODE 1: proj (+bias+resid)
template <int MODE>
__global__ __launch_bounds__(256, 2)
void gemm_kernel(const float* __restrict__ B,
                 const float* __restrict__ B2,
                 const float* __restrict__ B3,
                 const float* __restrict__ bias,
                 const float* __restrict__ resid,
                 float* __restrict__ Cout,
                 int Kdim, int Ndim)
{
    const int tid = threadIdx.x;
    const int mtile = blockIdx.y, ntile = blockIdx.x;
    const int e = blockIdx.z;

    const float* Bp = B;
    if (MODE == 0) Bp = (e == 0) ? B : (e == 1) ? B2 : B3;

    __shared__ float As[128][20];
    __shared__ float Bs[16][136];

    const int wid = tid >> 5, lane = tid & 31;
    const int wm = wid & 3, wn = wid >> 2;
    const int g = lane >> 2, t = lane & 3;

    const int arow = tid >> 1;
    const int akh  = (tid & 1) * 8;
    const float* aptr;
    {
        int r = mtile * 128 + arow;
        aptr = (MODE == 0) ? (g_xn + (size_t)r * CC) : (g_att + (size_t)r * CC);
    }
    const int bk = tid >> 4;
    const int bn = (tid & 15) * 8;
    const float* bptr;
    size_t bstride;
    if (MODE == 0) {
        int n = ntile * 128 + bn;
        int hh = n >> 6, d = n & 63;
        bptr = Bp + ((size_t)hh * Kdim + bk) * 64 + d;
        bstride = 64;
    } else {
        bptr = Bp + (size_t)bk * Ndim + ntile * 128 + bn;
        bstride = (size_t)Ndim;
    }

    float4 pa0, pa1, pb0, pb1;
    pa0 = *(const float4*)(aptr + akh);
    pa1 = *(const float4*)(aptr + akh + 4);
    pb0 = *(const float4*)(bptr);
    pb1 = *(const float4*)(bptr + 4);

    float acc[2][8][4];
#pragma unroll
    for (int i = 0; i < 2; i++)
#pragma unroll
        for (int j = 0; j < 8; j++)
#pragma unroll
            for (int q = 0; q < 4; q++) acc[i][j][q] = 0.f;

    for (int k0 = 0; k0 < Kdim; k0 += 16) {
        *(float4*)&As[arow][akh] =
            make_float4(to_tf32(pa0.x), to_tf32(pa0.y), to_tf32(pa0.z), to_tf32(pa0.w));
        *(float4*)&As[arow][akh + 4] =
            make_float4(to_tf32(pa1.x), to_tf32(pa1.y), to_tf32(pa1.z), to_tf32(pa1.w));
        *(float4*)&Bs[bk][bn] =
            make_float4(to_tf32(pb0.x), to_tf32(pb0.y), to_tf32(pb0.z), to_tf32(pb0.w));
        *(float4*)&Bs[bk][bn + 4] =
            make_float4(to_tf32(pb1.x), to_tf32(pb1.y), to_tf32(pb1.z), to_tf32(pb1.w));
        __syncthreads();

        if (k0 + 16 < Kdim) {
            pa0 = *(const float4*)(aptr + k0 + 16 + akh);
            pa1 = *(const float4*)(aptr + k0 + 16 + akh + 4);
            pb0 = *(const float4*)(bptr + (size_t)(k0 + 16) * bstride);
            pb1 = *(const float4*)(bptr + (size_t)(k0 + 16) * bstride + 4);
        }

#pragma unroll
        for (int ks = 0; ks < 16; ks += 8) {
            unsigned a[2][4];
#pragma unroll
            for (int mi = 0; mi < 2; mi++) {
                int m0 = wm * 32 + mi * 16;
                a[mi][0] = __float_as_uint(As[m0 + g][ks + t]);
                a[mi][1] = __float_as_uint(As[m0 + g + 8][ks + t]);
                a[mi][2] = __float_as_uint(As[m0 + g][ks + t + 4]);
                a[mi][3] = __float_as_uint(As[m0 + g + 8][ks + t + 4]);
            }
#pragma unroll
            for (int ni = 0; ni < 8; ni++) {
                int n0 = wn * 64 + ni * 8;
                unsigned b[2];
                b[0] = __float_as_uint(Bs[ks + t][n0 + g]);
                b[1] = __float_as_uint(Bs[ks + t + 4][n0 + g]);
                mma_tf32(acc[0][ni], a[0], b);
                mma_tf32(acc[1][ni], a[1], b);
            }
        }
        __syncthreads();
    }

#pragma unroll
    for (int mi = 0; mi < 2; mi++) {
#pragma unroll
        for (int rs = 0; rs < 2; rs++) {
            int m = mtile * 128 + wm * 32 + mi * 16 + g + rs * 8;
#pragma unroll
            for (int ni = 0; ni < 8; ni++) {
                int n = ntile * 128 + wn * 64 + ni * 8 + 2 * t;
                float v0 = acc[mi][ni][rs * 2], v1 = acc[mi][ni][rs * 2 + 1];
                if (MODE == 0) {
                    float* outbase = (e == 0) ? g_q : (e == 1) ? g_k : g_v;
                    int hh = n >> 6, d = n & 63;
                    float* op = outbase + ((size_t)hh * TT + m) * 64 + d;
                    // pre-round to tf32: attention consumes these raw (idempotent)
                    *(float2*)op = make_float2(to_tf32(v0), to_tf32(v1));
                } else {
                    size_t base = (size_t)m * CC + n;
                    float2 rv = *(const float2*)(resid + base);
                    *(float2*)(Cout + base) =
                        make_float2(v0 + bias[n] + rv.x, v1 + bias[n + 1] + rv.y);
                }
            }
        }
    }
}

// ------------------- fp16 GEMM (expert FFN, router-downstream) ---------------
template <int MODE>
__global__ __launch_bounds__(256, 2)
void gemm_h_kernel(const float* __restrict__ bias, int Kdim, int Ndim)
{
    const int tid = threadIdx.x;
    const int mtile = blockIdx.y, ntile = blockIdx.x;
    const int e = blockIdx.z;

    const int Mcount = g_count[e];
    if (mtile * 128 >= Mcount) return;
    const int* list = g_list + e * TT;
    const __half* hB = (MODE == 2) ? (h_W1 + (size_t)e * FF * CC)
                                   : (h_W2 + (size_t)e * CC * FF);
    const float* biasp = bias + (size_t)e * Ndim;

    __shared__ __align__(16) __half As[128 * 40];
    __shared__ __align__(16) __half Bs[128 * 40];

    const int wid = tid >> 5, lane = tid & 31;
    const int wm = wid & 3, wn = wid >> 2;
    const int g = lane >> 2, t = lane & 3;

    const int arow = tid >> 1;
    const int acol = (tid & 1) * 16;
    const float* aptr = nullptr;
    const __half* aptr_h = nullptr;
    {
        int r = mtile * 128 + arow;
        if (r < Mcount) {
            int slot = list[r];
            if (MODE == 2) aptr   = g_xn2  + (size_t)(slot >> 1) * CC;
            else           aptr_h = g_Hbuf + (size_t)slot * FF;
        }
    }
    const int brow = tid >> 1;
    const int bcol = (tid & 1) * 16;
    const __half* bptr = hB + (size_t)(ntile * 128 + brow) * Kdim + bcol;

    float4 pa0, pa1, pa2, pa3;
    uint4 ha0, ha1, hb0, hb1;
    pa0 = pa1 = pa2 = pa3 = make_float4(0.f, 0.f, 0.f, 0.f);
    ha0 = ha1 = make_uint4(0u, 0u, 0u, 0u);
    if (MODE == 3) {
        if (aptr_h) {
            ha0 = *(const uint4*)(aptr_h + acol);
            ha1 = *(const uint4*)(aptr_h + acol + 8);
        }
    } else if (aptr) {
        pa0 = *(const float4*)(aptr + acol);
        pa1 = *(const float4*)(aptr + acol + 4);
        pa2 = *(const float4*)(aptr + acol + 8);
        pa3 = *(const float4*)(aptr + acol + 12);
    }
    hb0 = *(const uint4*)(bptr);
    hb1 = *(const uint4*)(bptr + 8);

    float acc[2][8][4];
#pragma unroll
    for (int i = 0; i < 2; i++)
#pragma unroll
        for (int j = 0; j < 8; j++)
#pragma unroll
            for (int q = 0; q < 4; q++) acc[i][j][q] = 0.f;

    for (int k0 = 0; k0 < Kdim; k0 += 32) {
        if (MODE == 3) {
            *(uint4*)&As[arow * 40 + acol]     = ha0;
            *(uint4*)&As[arow * 40 + acol + 8] = ha1;
        } else {
            uint4 u0, u1;
            u0.x = packh2(pa0.x, pa0.y); u0.y = packh2(pa0.z, pa0.w);
            u0.z = packh2(pa1.x, pa1.y); u0.w = packh2(pa1.z, pa1.w);
            u1.x = packh2(pa2.x, pa2.y); u1.y = packh2(pa2.z, pa2.w);
            u1.z = packh2(pa3.x, pa3.y); u1.w = packh2(pa3.z, pa3.w);
            *(uint4*)&As[arow * 40 + acol]     = u0;
            *(uint4*)&As[arow * 40 + acol + 8] = u1;
        }
        *(uint4*)&Bs[brow * 40 + bcol]     = hb0;
        *(uint4*)&Bs[brow * 40 + bcol + 8] = hb1;
        __syncthreads();

        if (k0 + 32 < Kdim) {
            if (MODE == 3) {
                if (aptr_h) {
                    ha0 = *(const uint4*)(aptr_h + k0 + 32 + acol);
                    ha1 = *(const uint4*)(aptr_h + k0 + 32 + acol + 8);
                }
            } else if (aptr) {
                pa0 = *(const float4*)(aptr + k0 + 32 + acol);
                pa1 = *(const float4*)(aptr + k0 + 32 + acol + 4);
                pa2 = *(const float4*)(aptr + k0 + 32 + acol + 8);
                pa3 = *(const float4*)(aptr + k0 + 32 + acol + 12);
            }
            hb0 = *(const uint4*)(bptr + k0 + 32);
            hb1 = *(const uint4*)(bptr + k0 + 32 + 8);
        }

#pragma unroll
        for (int ks = 0; ks < 32; ks += 16) {
            unsigned a[2][4];
#pragma unroll
            for (int mi = 0; mi < 2; mi++) {
                int row = wm * 32 + mi * 16 + g;
                const __half* pa  = &As[row * 40 + ks + 2 * t];
                const __half* pa8 = &As[(row + 8) * 40 + ks + 2 * t];
                a[mi][0] = *(const unsigned*)pa;
                a[mi][1] = *(const unsigned*)pa8;
                a[mi][2] = *(const unsigned*)(pa + 8);
                a[mi][3] = *(const unsigned*)(pa8 + 8);
            }
#pragma unroll
            for (int ni = 0; ni < 8; ni++) {
                int n = wn * 64 + ni * 8 + g;
                const __half* pb = &Bs[n * 40 + ks + 2 * t];
                unsigned b0 = *(const unsigned*)pb;
                unsigned b1 = *(const unsigned*)(pb + 8);
                mma_f16(acc[0][ni], a[0], b0, b1);
                mma_f16(acc[1][ni], a[1], b0, b1);
            }
        }
        __syncthreads();
    }

#pragma unroll
    for (int mi = 0; mi < 2; mi++) {
#pragma unroll
        for (int rs = 0; rs < 2; rs++) {
            int m = mtile * 128 + wm * 32 + mi * 16 + g + rs * 8;
            if (m >= Mcount) continue;
            int slot = list[m];
#pragma unroll
            for (int ni = 0; ni < 8; ni++) {
                int n = ntile * 128 + wn * 64 + ni * 8 + 2 * t;
                float v0 = acc[mi][ni][rs * 2], v1 = acc[mi][ni][rs * 2 + 1];
                if (MODE == 2) {
                    __half2 hv = __floats2half2_rn(
                        fmaxf(v0 + biasp[n], 0.f),
                        fmaxf(v1 + biasp[n + 1], 0.f));
                    *(__half2*)(g_Hbuf + (size_t)slot * FF + n) = hv;
                } else {
                    float gte = g_gate[slot];
                    float* op = g_O2 + (size_t)slot * CC + n;
                    *(float2*)op = make_float2(gte * (v0 + biasp[n]),
                                               gte * (v1 + biasp[n + 1]));
                }
            }
        }
    }
}

// ---------------- Flash attention (causal, tf32 mma, cp.async pipeline) ------
// 128 threads (4 warps). Kb double-buffered, Vb single, XOR-swizzled 64x64
// tiles -> exactly 48KB static smem. V(kt) loads under S+softmax; K(kt+1)
// loads under P@V. Math order identical to round-12 (bitwise-same result).
__global__ __launch_bounds__(128, 3)
void attn_kernel()
{
    __shared__ float Kb[2][64 * 64];   // K tile (aliased as P after softmax)
    __shared__ float Vb[64 * 64];      // V tile

    const int qt = gridDim.x - 1 - blockIdx.x;   // heavy tiles first
    const int h  = blockIdx.y;
    const int tid = threadIdx.x;
    const int wid = tid >> 5, lane = tid & 31;
    const int g = lane >> 2, t = lane & 3;
    const int m0 = wid * 16;
    const float scale = 0.03125f;  // C^-0.5

    const int lr = tid >> 4;          // row offset within 8-row group
    const int lc = (tid & 15) * 4;    // col (float4)

    // ---- stage Q through Kb[0]; extract a-fragments (values already tf32) ----
    const float* Qg = g_q + ((size_t)h * TT + qt * 64) * DD;
#pragma unroll
    for (int j = 0; j < 8; j++) {
        int r = j * 8 + lr;
        float4 v = *(const float4*)(Qg + r * 64 + lc);
        *(float4*)&Kb[0][r * 64 + SWZF(r, lc)] = v;
    }
    __syncthreads();
    unsigned qfrag[8][4];
#pragma unroll
    for (int ks = 0; ks < 8; ks++) {
        int r0 = m0 + g, r1 = m0 + g + 8;
        qfrag[ks][0] = __float_as_uint(Kb[0][r0 * 64 + SWZF(r0, ks * 8 + t)]);
        qfrag[ks][1] = __float_as_uint(Kb[0][r1 * 64 + SWZF(r1, ks * 8 + t)]);
        qfrag[ks][2] = __float_as_uint(Kb[0][r0 * 64 + SWZF(r0, ks * 8 + t + 4)]);
        qfrag[ks][3] = __float_as_uint(Kb[0][r1 * 64 + SWZF(r1, ks * 8 + t + 4)]);
    }
    __syncthreads();   // all warps done with Kb[0] before K(0) overwrites it

    // issue K(0) -> Kb[0]
    {
        const float* Kg = g_k + (size_t)h * TT * DD;
#pragma unroll
        for (int j = 0; j < 8; j++) {
            int r = j * 8 + lr;
            cp_async16(smem_u32(&Kb[0][r * 64 + SWZF(r, lc)]), Kg + r * 64 + lc);
        }
        cp_commit();
    }

    float accO[8][4];
#pragma unroll
    for (int i = 0; i < 8; i++)
#pragma unroll
        for (int j = 0; j < 4; j++) accO[i][j] = 0.f;
    float mrow[2] = {-1e30f, -1e30f}, lrow[2] = {0.f, 0.f};

    for (int kt = 0; kt <= qt; kt++) {
        const int b = kt & 1;
        cp_wait_all();     // K(kt) landed
        __syncthreads();   // K visible to all; Vb + other K buffer free

        // issue V(kt) -> Vb (overlaps S + softmax)
        {
            const float* Vg = g_v + ((size_t)h * TT + kt * 64) * DD;
#pragma unroll
            for (int j = 0; j < 8; j++) {
                int r = j * 8 + lr;
                cp_async16(smem_u32(&Vb[r * 64 + SWZF(r, lc)]), Vg + r * 64 + lc);
            }
            cp_commit();
        }

        // ---- S = Q @ K^T ----
        float sacc[8][4];
#pragma unroll
        for (int i = 0; i < 8; i++)
#pragma unroll
            for (int j = 0; j < 4; j++) sacc[i][j] = 0.f;
#pragma unroll
        for (int ks = 0; ks < 8; ks++) {
#pragma unroll
            for (int ni = 0; ni < 8; ni++) {
                int rn = ni * 8 + g;
                unsigned bb[2];
                bb[0] = __float_as_uint(Kb[b][rn * 64 + SWZF(rn, ks * 8 + t)]);
                bb[1] = __float_as_uint(Kb[b][rn * 64 + SWZF(rn, ks * 8 + t + 4)]);
                mma_tf32(sacc[ni], qfrag[ks], bb);
            }
        }

        // ---- scale + causal mask + online softmax ----
#pragma unroll
        for (int r = 0; r < 2; r++) {
            int rowl = m0 + g + r * 8;
            float vmax = -1e30f;
#pragma unroll
            for (int ni = 0; ni < 8; ni++) {
                float s0 = sacc[ni][r * 2] * scale;
                float s1 = sacc[ni][r * 2 + 1] * scale;
                if (kt == qt) {
                    int c0 = ni * 8 + 2 * t;
                    if (c0 > rowl)     s0 = -1e30f;
                    if (c0 + 1 > rowl) s1 = -1e30f;
                }
                sacc[ni][r * 2] = s0; sacc[ni][r * 2 + 1] = s1;
                vmax = fmaxf(vmax, fmaxf(s0, s1));
            }
            vmax = fmaxf(vmax, __shfl_xor_sync(0xffffffffu, vmax, 1));
            vmax = fmaxf(vmax, __shfl_xor_sync(0xffffffffu, vmax, 2));
            float mn  = fmaxf(mrow[r], vmax);
            float fac = __expf(mrow[r] - mn);
            float sum = 0.f;
#pragma unroll
            for (int ni = 0; ni < 8; ni++) {
                float p0 = __expf(sacc[ni][r * 2] - mn);
                float p1 = __expf(sacc[ni][r * 2 + 1] - mn);
                sacc[ni][r * 2] = p0; sacc[ni][r * 2 + 1] = p1;
                sum += p0 + p1;
            }
            sum += __shfl_xor_sync(0xffffffffu, sum, 1);
            sum += __shfl_xor_sync(0xffffffffu, sum, 2);
            mrow[r] = mn;
            lrow[r] = lrow[r] * fac + sum;
#pragma unroll
            for (int ni = 0; ni < 8; ni++) {
                accO[ni][r * 2]     *= fac;
                accO[ni][r * 2 + 1] *= fac;
            }
        }

        cp_wait_all();     // V(kt) landed
        __syncthreads();   // all warps done reading Kb[b] as K; V visible

        // ---- write P into Kb[b] ----
        float* Ps = Kb[b];
        {
            int r0 = m0 + g, r1 = m0 + g + 8;
#pragma unroll
            for (int ni = 0; ni < 8; ni++) {
                Ps[r0 * 64 + SWZF(r0, ni * 8 + 2 * t)]     = to_tf32(sacc[ni][0]);
                Ps[r0 * 64 + SWZF(r0, ni * 8 + 2 * t + 1)] = to_tf32(sacc[ni][1]);
                Ps[r1 * 64 + SWZF(r1, ni * 8 + 2 * t)]     = to_tf32(sacc[ni][2]);
                Ps[r1 * 64 + SWZF(r1, ni * 8 + 2 * t + 1)] = to_tf32(sacc[ni][3]);
            }
        }

        // issue K(kt+1) -> Kb[b^1] (overlaps P @ V)
        if (kt < qt) {
            const float* Kg = g_k + ((size_t)h * TT + (kt + 1) * 64) * DD;
#pragma unroll
            for (int j = 0; j < 8; j++) {
                int r = j * 8 + lr;
                cp_async16(smem_u32(&Kb[b ^ 1][r * 64 + SWZF(r, lc)]),
                           Kg + r * 64 + lc);
            }
            cp_commit();
        }
        __syncwarp();      // own warp's P rows visible (only own rows read)

        // ---- O += P @ V ----
        {
            int r0 = m0 + g, r1 = m0 + g + 8;
#pragma unroll
            for (int ks = 0; ks < 8; ks++) {
                unsigned a[4];
                a[0] = __float_as_uint(Ps[r0 * 64 + SWZF(r0, ks * 8 + t)]);
                a[1] = __float_as_uint(Ps[r1 * 64 + SWZF(r1, ks * 8 + t)]);
                a[2] = __float_as_uint(Ps[r0 * 64 + SWZF(r0, ks * 8 + t + 4)]);
                a[3] = __float_as_uint(Ps[r1 * 64 + SWZF(r1, ks * 8 + t + 4)]);
#pragma unroll
                for (int ni = 0; ni < 8; ni++) {
                    int rs0 = ks * 8 + t, rs1 = ks * 8 + t + 4;
                    unsigned bb[2];
                    bb[0] = __float_as_uint(Vb[rs0 * 64 + SWZF(rs0, ni * 8 + g)]);
                    bb[1] = __float_as_uint(Vb[rs1 * 64 + SWZF(rs1, ni * 8 + g)]);
                    mma_tf32(accO[ni], a, bb);
                }
            }
        }
    }

#pragma unroll
    for (int r = 0; r < 2; r++) {
        float inv = 1.f / lrow[r];
        int row = qt * 64 + m0 + g + r * 8;
#pragma unroll
        for (int ni = 0; ni < 8; ni++) {
            int col = h * 64 + ni * 8 + 2 * t;
            *(float2*)(g_att + (size_t)row * CC + col) =
                make_float2(accO[ni][r * 2] * inv, accO[ni][r * 2 + 1] * inv);
        }
    }
}

// ------------------------------ Router ---------------------------------------
__global__ void zero_counts_kernel() { if (threadIdx.x < EE) g_count[threadIdx.x] = 0; }

__global__ void router_kernel(const float* __restrict__ Wr, const float* __restrict__ br,
                              const float* __restrict__ Wn, const float* __restrict__ bn,
                              const float* __restrict__ noise)
{
    int t = blockIdx.x * 8 + (threadIdx.x >> 5);
    int lane = threadIdx.x & 31;
    const float* xr = g_xn2 + (size_t)t * CC;
    float ar[8] = {0,0,0,0,0,0,0,0}, an[8] = {0,0,0,0,0,0,0,0};
    for (int c = lane; c < CC; c += 32) {
        float xv = xr[c];
        float4 w0 = *(const float4*)(Wr + c * 8);
        float4 w1 = *(const float4*)(Wr + c * 8 + 4);
        ar[0] += xv * w0.x; ar[1] += xv * w0.y; ar[2] += xv * w0.z; ar[3] += xv * w0.w;
        ar[4] += xv * w1.x; ar[5] += xv * w1.y; ar[6] += xv * w1.z; ar[7] += xv * w1.w;
        float4 n0 = *(const float4*)(Wn + c * 8);
        float4 n1 = *(const float4*)(Wn + c * 8 + 4);
        an[0] += xv * n0.x; an[1] += xv * n0.y; an[2] += xv * n0.z; an[3] += xv * n0.w;
        an[4] += xv * n1.x; an[5] += xv * n1.y; an[6] += xv * n1.z; an[7] += xv * n1.w;
    }
#pragma unroll
    for (int e = 0; e < 8; e++) {
#pragma unroll
        for (int o = 16; o > 0; o >>= 1) {
            ar[e] += __shfl_xor_sync(0xffffffffu, ar[e], o);
            an[e] += __shfl_xor_sync(0xffffffffu, an[e], o);
        }
    }
    if (lane == 0) {
        float noisy[8];
#pragma unroll
        for (int e = 0; e < 8; e++) {
            float l  = ar[e] + br[e];
            float nl = an[e] + bn[e];
            float sp = (nl > 20.f) ? nl : log1pf(expf(nl));
            noisy[e] = l + noise[t * 8 + e] * sp;
        }
        int i1 = 0;
        for (int e = 1; e < 8; e++) if (noisy[e] > noisy[i1]) i1 = e;
        int i2 = (i1 == 0) ? 1 : 0;
        for (int e = 0; e < 8; e++)
            if (e != i1 && noisy[e] > noisy[i2]) i2 = e;
        float ee = expf(noisy[i2] - noisy[i1]);
        float z  = 1.f + ee;
        float g1 = 1.f / z, g2 = ee / z;
        int p1 = atomicAdd(&g_count[i1], 1);
        g_list[i1 * TT + p1] = t * 2;     g_gate[t * 2]     = g1;
        int p2 = atomicAdd(&g_count[i2], 1);
        g_list[i2 * TT + p2] = t * 2 + 1; g_gate[t * 2 + 1] = g2;
    }
}

// ------------------------------ Combine --------------------------------------
__global__ void combine_kernel(float* __restrict__ out)
{
    int t = blockIdx.x;
    size_t b0 = (size_t)(t * 2) * CC;
    size_t b1 = (size_t)(t * 2 + 1) * CC;
    for (int c = threadIdx.x; c < CC; c += 256)
        out[(size_t)t * CC + c] += g_O2[b0 + c] + g_O2[b1 + c];
}

// ------------------------------ launch ---------------------------------------
extern "C" void kernel_launch(void* const* d_in, const int* in_sizes, int n_in,
                              void* d_out, int out_size)
{
    (void)in_sizes; (void)n_in; (void)out_size;
    const float* x     = (const float*)d_in[0];
    const float* noise = (const float*)d_in[1];
    const float* ln1_g = (const float*)d_in[2];
    const float* ln1_b = (const float*)d_in[3];
    const float* ln2_g = (const float*)d_in[4];
    const float* ln2_b = (const float*)d_in[5];
    const float* Wq    = (const float*)d_in[6];
    const float* Wk    = (const float*)d_in[7];
    const float* Wv    = (const float*)d_in[8];
    const float* Wproj = (const float*)d_in[9];
    const float* bproj = (const float*)d_in[10];
    const float* Wr    = (const float*)d_in[11];
    const float* br    = (const float*)d_in[12];
    const float* Wn    = (const float*)d_in[13];
    const float* bn    = (const float*)d_in[14];
    const float* W1    = (const float*)d_in[15];
    const float* b1    = (const float*)d_in[16];
    const float* W2    = (const float*)d_in[17];
    const float* b2    = (const float*)d_in[18];
    float* out = (float*)d_out;

    __half *p_hW1, *p_hW2;
    cudaGetSymbolAddress((void**)&p_hW1, h_W1);
    cudaGetSymbolAddress((void**)&p_hW2, h_W2);

    dim3 tb(32, 8);
    transpose_h_kernel<<<dim3(FF / 32, CC / 32, EE), tb>>>(
        W1, p_hW1, CC, FF, (size_t)CC * FF, (size_t)FF * CC);
    transpose_h_kernel<<<dim3(CC / 32, FF / 32, EE), tb>>>(
        W2, p_hW2, FF, CC, (size_t)FF * CC, (size_t)CC * FF);

    ln_kernel<0><<<TT, 256>>>(x, ln1_g, ln1_b);

    gemm_kernel<0><<<dim3(CC / 128, TT / 128, 3), 256>>>(
        Wq, Wk, Wv, nullptr, nullptr, nullptr, CC, CC);

    attn_kernel<<<dim3(TT / 64, HH), 128>>>();

    gemm_kernel<1><<<dim3(CC / 128, TT / 128), 256>>>(
        Wproj, nullptr, nullptr, bproj, x, out, CC, CC);

    ln_kernel<1><<<TT, 256>>>(out, ln2_g, ln2_b);

    zero_counts_kernel<<<1, 32>>>();
    router_kernel<<<TT / 8, 256>>>(Wr, br, Wn, bn, noise);

    gemm_h_kernel<2><<<dim3(FF / 128, 16, EE), 256>>>(b1, CC, FF);
    gemm_h_kernel<3><<<dim3(CC / 128, 16, EE), 256>>>(b2, FF, CC);

    combine_kernel<<<TT, 256>>>(out);
}

// round 16
// speedup vs baseline: 1.1079x; 1.1079x over previous
#include <cuda_runtime.h>
#include <cuda_fp16.h>
#include <math.h>

#define TT 2048
#define CC 1024
#define HH 16
#define DD 64
#define EE 8
#define FF 4096

// ------------------------- scratch (device globals; no allocs) ---------------
__device__ float g_xn  [TT * CC];          // LN1 output
__device__ float g_q   [HH * TT * DD];     // (H,T,D) fp32, PRE-ROUNDED to tf32
__device__ float g_k   [HH * TT * DD];
__device__ float g_v   [HH * TT * DD];
__device__ float g_att [TT * CC];          // concat-head attention output
__device__ float g_xn2 [TT * CC];          // LN2 output
__device__ __half g_Hbuf[(size_t)TT * 2 * FF]; // expert hidden (fp16), slot-indexed
__device__ float g_O2  [(size_t)TT * 2 * CC];  // expert output * gate, slot-indexed
__device__ float g_gate[TT * 2];
__device__ int   g_list[EE * TT];
__device__ int   g_count[EE];

// fp16 transposed expert weights: stored [n][k] (k contiguous)
__device__ __half h_W1[(size_t)EE * FF * CC]; // per e: [n=F][k=C]
__device__ __half h_W2[(size_t)EE * CC * FF]; // per e: [n=C][k=F]

// ------------------------------ helpers --------------------------------------
__device__ __forceinline__ float to_tf32(float x) {
    float r;
    asm("cvt.rna.tf32.f32 %0, %1;" : "=f"(r) : "f"(x));
    return r;
}

__device__ __forceinline__ void mma_tf32(float* c, const unsigned* a, const unsigned* b) {
    asm volatile(
        "mma.sync.aligned.m16n8k8.row.col.f32.tf32.tf32.f32 "
        "{%0,%1,%2,%3}, {%4,%5,%6,%7}, {%8,%9}, {%0,%1,%2,%3};"
        : "+f"(c[0]), "+f"(c[1]), "+f"(c[2]), "+f"(c[3])
        : "r"(a[0]), "r"(a[1]), "r"(a[2]), "r"(a[3]), "r"(b[0]), "r"(b[1]));
}

__device__ __forceinline__ void mma_f16(float* c, const unsigned* a,
                                        unsigned b0, unsigned b1) {
    asm volatile(
        "mma.sync.aligned.m16n8k16.row.col.f32.f16.f16.f32 "
        "{%0,%1,%2,%3}, {%4,%5,%6,%7}, {%8,%9}, {%0,%1,%2,%3};"
        : "+f"(c[0]), "+f"(c[1]), "+f"(c[2]), "+f"(c[3])
        : "r"(a[0]), "r"(a[1]), "r"(a[2]), "r"(a[3]), "r"(b0), "r"(b1));
}

__device__ __forceinline__ unsigned packh2(float x, float y) {
    __half2 h = __floats2half2_rn(x, y);
    return *(unsigned*)&h;
}

__device__ __forceinline__ unsigned smem_u32(const void* p) {
    return (unsigned)__cvta_generic_to_shared(p);
}

// ldmatrix x4 (b16, no transpose)
__device__ __forceinline__ void ldsm_x4(unsigned& r0, unsigned& r1,
                                        unsigned& r2, unsigned& r3, unsigned addr) {
    asm volatile("ldmatrix.sync.aligned.m8n8.x4.shared.b16 {%0,%1,%2,%3}, [%4];"
        : "=r"(r0), "=r"(r1), "=r"(r2), "=r"(r3) : "r"(addr));
}

// --------------------- weight transpose+convert (fp32 -> fp16 [n][k]) --------
__global__ void transpose_h_kernel(const float* __restrict__ src,
                                   __half* __restrict__ dst,
                                   int rows, int cols,
                                   size_t sstride, size_t dstride)
{
    __shared__ __half tile[32][33];
    const size_t b = blockIdx.z;
    const int c0 = blockIdx.x * 32, r0 = blockIdx.y * 32;
    const int tx = threadIdx.x, ty = threadIdx.y;
#pragma unroll
    for (int i = 0; i < 4; i++) {
        int r = r0 + ty + i * 8;
        tile[ty + i * 8][tx] =
            __float2half(src[b * sstride + (size_t)r * cols + c0 + tx]);
    }
    __syncthreads();
#pragma unroll
    for (int i = 0; i < 4; i++) {
        int c = c0 + ty + i * 8;
        dst[b * dstride + (size_t)c * rows + r0 + tx] = tile[tx][ty + i * 8];
    }
}

// ------------------------------ LayerNorm ------------------------------------
template <int PHASE>
__global__ void ln_kernel(const float* __restrict__ x,
                          const float* __restrict__ gamma,
                          const float* __restrict__ beta)
{
    int t = blockIdx.x;
    const float* xr = x + (size_t)t * CC;
    float s = 0.f, s2 = 0.f;
    for (int c = threadIdx.x; c < CC; c += 256) {
        float v = xr[c]; s += v; s2 += v * v;
    }
#pragma unroll
    for (int o = 16; o > 0; o >>= 1) {
        s  += __shfl_xor_sync(0xffffffffu, s,  o);
        s2 += __shfl_xor_sync(0xffffffffu, s2, o);
    }
    __shared__ float sm[8], sm2[8];
    __shared__ float smean, srstd;
    if ((threadIdx.x & 31) == 0) { sm[threadIdx.x >> 5] = s; sm2[threadIdx.x >> 5] = s2; }
    __syncthreads();
    if (threadIdx.x == 0) {
        float a = 0.f, a2 = 0.f;
        for (int i = 0; i < 8; i++) { a += sm[i]; a2 += sm2[i]; }
        float m   = a * (1.f / CC);
        float var = a2 * (1.f / CC) - m * m;
        smean = m; srstd = rsqrtf(var + 1e-5f);
    }
    __syncthreads();
    float m = smean, r = srstd;
    float* out = (PHASE == 0) ? g_xn : g_xn2;
    for (int c = threadIdx.x; c < CC; c += 256)
        out[(size_t)t * CC + c] = (xr[c] - m) * r * gamma[c] + beta[c];
}

// ------------------------- tf32 GEMM (router-upstream path) ------------------
// MODE 0: QKV fused  (out pre-rounded to tf32)   MODE 1: proj (+bias+resid)
template <int MODE>
__global__ __launch_bounds__(256, 2)
void gemm_kernel(const float* __restrict__ B,
                 const float* __restrict__ B2,
                 const float* __restrict__ B3,
                 const float* __restrict__ bias,
                 const float* __restrict__ resid,
                 float* __restrict__ Cout,
                 int Kdim, int Ndim)
{
    const int tid = threadIdx.x;
    const int mtile = blockIdx.y, ntile = blockIdx.x;
    const int e = blockIdx.z;

    const float* Bp = B;
    if (MODE == 0) Bp = (e == 0) ? B : (e == 1) ? B2 : B3;

    __shared__ float As[128][20];
    __shared__ float Bs[16][136];

    const int wid = tid >> 5, lane = tid & 31;
    const int wm = wid & 3, wn = wid >> 2;
    const int g = lane >> 2, t = lane & 3;

    const int arow = tid >> 1;
    const int akh  = (tid & 1) * 8;
    const float* aptr;
    {
        int r = mtile * 128 + arow;
        aptr = (MODE == 0) ? (g_xn + (size_t)r * CC) : (g_att + (size_t)r * CC);
    }
    const int bk = tid >> 4;
    const int bn = (tid & 15) * 8;
    const float* bptr;
    size_t bstride;
    if (MODE == 0) {
        int n = ntile * 128 + bn;
        int hh = n >> 6, d = n & 63;
        bptr = Bp + ((size_t)hh * Kdim + bk) * 64 + d;
        bstride = 64;
    } else {
        bptr = Bp + (size_t)bk * Ndim + ntile * 128 + bn;
        bstride = (size_t)Ndim;
    }

    float4 pa0, pa1, pb0, pb1;
    pa0 = *(const float4*)(aptr + akh);
    pa1 = *(const float4*)(aptr + akh + 4);
    pb0 = *(const float4*)(bptr);
    pb1 = *(const float4*)(bptr + 4);

    float acc[2][8][4];
#pragma unroll
    for (int i = 0; i < 2; i++)
#pragma unroll
        for (int j = 0; j < 8; j++)
#pragma unroll
            for (int q = 0; q < 4; q++) acc[i][j][q] = 0.f;

    for (int k0 = 0; k0 < Kdim; k0 += 16) {
        *(float4*)&As[arow][akh] =
            make_float4(to_tf32(pa0.x), to_tf32(pa0.y), to_tf32(pa0.z), to_tf32(pa0.w));
        *(float4*)&As[arow][akh + 4] =
            make_float4(to_tf32(pa1.x), to_tf32(pa1.y), to_tf32(pa1.z), to_tf32(pa1.w));
        *(float4*)&Bs[bk][bn] =
            make_float4(to_tf32(pb0.x), to_tf32(pb0.y), to_tf32(pb0.z), to_tf32(pb0.w));
        *(float4*)&Bs[bk][bn + 4] =
            make_float4(to_tf32(pb1.x), to_tf32(pb1.y), to_tf32(pb1.z), to_tf32(pb1.w));
        __syncthreads();

        if (k0 + 16 < Kdim) {
            pa0 = *(const float4*)(aptr + k0 + 16 + akh);
            pa1 = *(const float4*)(aptr + k0 + 16 + akh + 4);
            pb0 = *(const float4*)(bptr + (size_t)(k0 + 16) * bstride);
            pb1 = *(const float4*)(bptr + (size_t)(k0 + 16) * bstride + 4);
        }

#pragma unroll
        for (int ks = 0; ks < 16; ks += 8) {
            unsigned a[2][4];
#pragma unroll
            for (int mi = 0; mi < 2; mi++) {
                int m0 = wm * 32 + mi * 16;
                a[mi][0] = __float_as_uint(As[m0 + g][ks + t]);
                a[mi][1] = __float_as_uint(As[m0 + g + 8][ks + t]);
                a[mi][2] = __float_as_uint(As[m0 + g][ks + t + 4]);
                a[mi][3] = __float_as_uint(As[m0 + g + 8][ks + t + 4]);
            }
#pragma unroll
            for (int ni = 0; ni < 8; ni++) {
                int n0 = wn * 64 + ni * 8;
                unsigned b[2];
                b[0] = __float_as_uint(Bs[ks + t][n0 + g]);
                b[1] = __float_as_uint(Bs[ks + t + 4][n0 + g]);
                mma_tf32(acc[0][ni], a[0], b);
                mma_tf32(acc[1][ni], a[1], b);
            }
        }
        __syncthreads();
    }

#pragma unroll
    for (int mi = 0; mi < 2; mi++) {
#pragma unroll
        for (int rs = 0; rs < 2; rs++) {
            int m = mtile * 128 + wm * 32 + mi * 16 + g + rs * 8;
#pragma unroll
            for (int ni = 0; ni < 8; ni++) {
                int n = ntile * 128 + wn * 64 + ni * 8 + 2 * t;
                float v0 = acc[mi][ni][rs * 2], v1 = acc[mi][ni][rs * 2 + 1];
                if (MODE == 0) {
                    float* outbase = (e == 0) ? g_q : (e == 1) ? g_k : g_v;
                    int hh = n >> 6, d = n & 63;
                    float* op = outbase + ((size_t)hh * TT + m) * 64 + d;
                    // pre-round to tf32: attention consumes these raw (idempotent)
                    *(float2*)op = make_float2(to_tf32(v0), to_tf32(v1));
                } else {
                    size_t base = (size_t)m * CC + n;
                    float2 rv = *(const float2*)(resid + base);
                    *(float2*)(Cout + base) =
                        make_float2(v0 + bias[n] + rv.x, v1 + bias[n + 1] + rv.y);
                }
            }
        }
    }
}

// ------------------- fp16 GEMM (expert FFN, router-downstream) ---------------
// Tile 128x128, BK=32, 256 threads, m16n8k16, fragments via ldmatrix.x4
// (stride-40-half rows: 80B pitch -> 8-row LDSM phases hit all 32 banks once).
template <int MODE>
__global__ __launch_bounds__(256, 2)
void gemm_h_kernel(const float* __restrict__ bias, int Kdim, int Ndim)
{
    const int tid = threadIdx.x;
    const int mtile = blockIdx.y, ntile = blockIdx.x;
    const int e = blockIdx.z;

    const int Mcount = g_count[e];
    if (mtile * 128 >= Mcount) return;
    const int* list = g_list + e * TT;
    const __half* hB = (MODE == 2) ? (h_W1 + (size_t)e * FF * CC)
                                   : (h_W2 + (size_t)e * CC * FF);
    const float* biasp = bias + (size_t)e * Ndim;

    __shared__ __align__(16) __half As[128 * 40];
    __shared__ __align__(16) __half Bs[128 * 40];

    const int wid = tid >> 5, lane = tid & 31;
    const int wm = wid & 3, wn = wid >> 2;
    const int g = lane >> 2, t = lane & 3;

    const int arow = tid >> 1;
    const int acol = (tid & 1) * 16;
    const float* aptr = nullptr;
    const __half* aptr_h = nullptr;
    {
        int r = mtile * 128 + arow;
        if (r < Mcount) {
            int slot = list[r];
            if (MODE == 2) aptr   = g_xn2  + (size_t)(slot >> 1) * CC;
            else           aptr_h = g_Hbuf + (size_t)slot * FF;
        }
    }
    const int brow = tid >> 1;
    const int bcol = (tid & 1) * 16;
    const __half* bptr = hB + (size_t)(ntile * 128 + brow) * Kdim + bcol;

    // ldmatrix per-lane base byte addresses (lanes 0-15: rows, 16-31: +8 cols)
    const unsigned a_base = smem_u32(As) +
        (((wm * 32 + (lane & 15)) * 40 + ((lane >> 4) << 3)) << 1);
    const unsigned b_base = smem_u32(Bs) +
        (((wn * 64 + (lane & 15)) * 40 + ((lane >> 4) << 3)) << 1);

    float4 pa0, pa1, pa2, pa3;
    uint4 ha0, ha1, hb0, hb1;
    pa0 = pa1 = pa2 = pa3 = make_float4(0.f, 0.f, 0.f, 0.f);
    ha0 = ha1 = make_uint4(0u, 0u, 0u, 0u);
    if (MODE == 3) {
        if (aptr_h) {
            ha0 = *(const uint4*)(aptr_h + acol);
            ha1 = *(const uint4*)(aptr_h + acol + 8);
        }
    } else if (aptr) {
        pa0 = *(const float4*)(aptr + acol);
        pa1 = *(const float4*)(aptr + acol + 4);
        pa2 = *(const float4*)(aptr + acol + 8);
        pa3 = *(const float4*)(aptr + acol + 12);
    }
    hb0 = *(const uint4*)(bptr);
    hb1 = *(const uint4*)(bptr + 8);

    float acc[2][8][4];
#pragma unroll
    for (int i = 0; i < 2; i++)
#pragma unroll
        for (int j = 0; j < 8; j++)
#pragma unroll
            for (int q = 0; q < 4; q++) acc[i][j][q] = 0.f;

    for (int k0 = 0; k0 < Kdim; k0 += 32) {
        if (MODE == 3) {
            *(uint4*)&As[arow * 40 + acol]     = ha0;
            *(uint4*)&As[arow * 40 + acol + 8] = ha1;
        } else {
            uint4 u0, u1;
            u0.x = packh2(pa0.x, pa0.y); u0.y = packh2(pa0.z, pa0.w);
            u0.z = packh2(pa1.x, pa1.y); u0.w = packh2(pa1.z, pa1.w);
            u1.x = packh2(pa2.x, pa2.y); u1.y = packh2(pa2.z, pa2.w);
            u1.z = packh2(pa3.x, pa3.y); u1.w = packh2(pa3.z, pa3.w);
            *(uint4*)&As[arow * 40 + acol]     = u0;
            *(uint4*)&As[arow * 40 + acol + 8] = u1;
        }
        *(uint4*)&Bs[brow * 40 + bcol]     = hb0;
        *(uint4*)&Bs[brow * 40 + bcol + 8] = hb1;
        __syncthreads();

        if (k0 + 32 < Kdim) {
            if (MODE == 3) {
                if (aptr_h) {
                    ha0 = *(const uint4*)(aptr_h + k0 + 32 + acol);
                    ha1 = *(const uint4*)(aptr_h + k0 + 32 + acol + 8);
                }
            } else if (aptr) {
                pa0 = *(const float4*)(aptr + k0 + 32 + acol);
                pa1 = *(const float4*)(aptr + k0 + 32 + acol + 4);
                pa2 = *(const float4*)(aptr + k0 + 32 + acol + 8);
                pa3 = *(const float4*)(aptr + k0 + 32 + acol + 12);
            }
            hb0 = *(const uint4*)(bptr + k0 + 32);
            hb1 = *(const uint4*)(bptr + k0 + 32 + 8);
        }

#pragma unroll
        for (int ks = 0; ks < 32; ks += 16) {
            unsigned a[2][4];
            ldsm_x4(a[0][0], a[0][1], a[0][2], a[0][3], a_base + (ks << 1));
            ldsm_x4(a[1][0], a[1][1], a[1][2], a[1][3],
                    a_base + ((16 * 40 + ks) << 1));
#pragma unroll
            for (int p = 0; p < 4; p++) {
                unsigned r0, r1, r2, r3;
                ldsm_x4(r0, r1, r2, r3, b_base + ((p * 16 * 40 + ks) << 1));
                mma_f16(acc[0][2 * p],     a[0], r0, r2);
                mma_f16(acc[1][2 * p],     a[1], r0, r2);
                mma_f16(acc[0][2 * p + 1], a[0], r1, r3);
                mma_f16(acc[1][2 * p + 1], a[1], r1, r3);
            }
        }
        __syncthreads();
    }

#pragma unroll
    for (int mi = 0; mi < 2; mi++) {
#pragma unroll
        for (int rs = 0; rs < 2; rs++) {
            int m = mtile * 128 + wm * 32 + mi * 16 + g + rs * 8;
            if (m >= Mcount) continue;
            int slot = list[m];
#pragma unroll
            for (int ni = 0; ni < 8; ni++) {
                int n = ntile * 128 + wn * 64 + ni * 8 + 2 * t;
                float v0 = acc[mi][ni][rs * 2], v1 = acc[mi][ni][rs * 2 + 1];
                if (MODE == 2) {
                    __half2 hv = __floats2half2_rn(
                        fmaxf(v0 + biasp[n], 0.f),
                        fmaxf(v1 + biasp[n + 1], 0.f));
                    *(__half2*)(g_Hbuf + (size_t)slot * FF + n) = hv;
                } else {
                    float gte = g_gate[slot];
                    float* op = g_O2 + (size_t)slot * CC + n;
                    *(float2*)op = make_float2(gte * (v0 + biasp[n]),
                                               gte * (v1 + biasp[n + 1]));
                }
            }
        }
    }
}

// ------------- Flash attention (causal, tf32 mma) — round-12 version ---------
// Inputs pre-rounded to tf32 by QKV epilogue, so loads are raw copies.
__global__ __launch_bounds__(128, 3)
void attn_kernel()
{
    __shared__ float Ks[64 * 68];   // K tile, later aliased as P
    __shared__ float Vs[64 * 68];   // V tile

    const int qt = gridDim.x - 1 - blockIdx.x;   // heavy tiles first
    const int h  = blockIdx.y;
    const int tid = threadIdx.x;
    const int wid = tid >> 5, lane = tid & 31;
    const int g = lane >> 2, t = lane & 3;
    const int m0 = wid * 16;
    const float scale = 0.03125f;  // C^-0.5

    // ---- stage Q through Ks once, extract a-fragments into registers ----
    const float* Qg = g_q + ((size_t)h * TT + qt * 64) * DD;
#pragma unroll
    for (int j = 0; j < 8; j++) {
        int idx = j * 512 + tid * 4;
        int r = idx >> 6, d = idx & 63;
        *(float4*)(Ks + r * 68 + d) = *(const float4*)(Qg + idx);
    }
    __syncthreads();
    unsigned qfrag[8][4];
#pragma unroll
    for (int ks = 0; ks < 8; ks++) {
        qfrag[ks][0] = __float_as_uint(Ks[(m0 + g) * 68 + ks * 8 + t]);
        qfrag[ks][1] = __float_as_uint(Ks[(m0 + g + 8) * 68 + ks * 8 + t]);
        qfrag[ks][2] = __float_as_uint(Ks[(m0 + g) * 68 + ks * 8 + t + 4]);
        qfrag[ks][3] = __float_as_uint(Ks[(m0 + g + 8) * 68 + ks * 8 + t + 4]);
    }

    float accO[8][4];
#pragma unroll
    for (int i = 0; i < 8; i++)
#pragma unroll
        for (int j = 0; j < 4; j++) accO[i][j] = 0.f;
    float mrow[2] = {-1e30f, -1e30f}, lrow[2] = {0.f, 0.f};

    for (int kt = 0; kt <= qt; kt++) {
        __syncthreads();   // prior use of Ks(P)/Vs complete (iter0: Q extraction)
        const float* Kg = g_k + ((size_t)h * TT + kt * 64) * DD;
        const float* Vg = g_v + ((size_t)h * TT + kt * 64) * DD;
#pragma unroll
        for (int j = 0; j < 8; j++) {
            int idx = j * 512 + tid * 4;
            int r = idx >> 6, d = idx & 63;
            *(float4*)(Ks + r * 68 + d) = *(const float4*)(Kg + idx);
            *(float4*)(Vs + r * 68 + d) = *(const float4*)(Vg + idx);
        }
        __syncthreads();

        // ---- S = Q @ K^T ----
        float sacc[8][4];
#pragma unroll
        for (int i = 0; i < 8; i++)
#pragma unroll
            for (int j = 0; j < 4; j++) sacc[i][j] = 0.f;
#pragma unroll
        for (int ks = 0; ks < 8; ks++) {
#pragma unroll
            for (int ni = 0; ni < 8; ni++) {
                unsigned b[2];
                b[0] = __float_as_uint(Ks[(ni * 8 + g) * 68 + ks * 8 + t]);
                b[1] = __float_as_uint(Ks[(ni * 8 + g) * 68 + ks * 8 + t + 4]);
                mma_tf32(sacc[ni], qfrag[ks], b);
            }
        }

        // ---- scale + causal mask + online softmax ----
#pragma unroll
        for (int r = 0; r < 2; r++) {
            int rowl = m0 + g + r * 8;
            float vmax = -1e30f;
#pragma unroll
            for (int ni = 0; ni < 8; ni++) {
                float s0 = sacc[ni][r * 2] * scale;
                float s1 = sacc[ni][r * 2 + 1] * scale;
                if (kt == qt) {
                    int c0 = ni * 8 + 2 * t;
                    if (c0 > rowl)     s0 = -1e30f;
                    if (c0 + 1 > rowl) s1 = -1e30f;
                }
                sacc[ni][r * 2] = s0; sacc[ni][r * 2 + 1] = s1;
                vmax = fmaxf(vmax, fmaxf(s0, s1));
            }
            vmax = fmaxf(vmax, __shfl_xor_sync(0xffffffffu, vmax, 1));
            vmax = fmaxf(vmax, __shfl_xor_sync(0xffffffffu, vmax, 2));
            float mn  = fmaxf(mrow[r], vmax);
            float fac = __expf(mrow[r] - mn);
            float sum = 0.f;
#pragma unroll
            for (int ni = 0; ni < 8; ni++) {
                float p0 = __expf(sacc[ni][r * 2] - mn);
                float p1 = __expf(sacc[ni][r * 2 + 1] - mn);
                sacc[ni][r * 2] = p0; sacc[ni][r * 2 + 1] = p1;
                sum += p0 + p1;
            }
            sum += __shfl_xor_sync(0xffffffffu, sum, 1);
            sum += __shfl_xor_sync(0xffffffffu, sum, 2);
            mrow[r] = mn;
            lrow[r] = lrow[r] * fac + sum;
#pragma unroll
            for (int ni = 0; ni < 8; ni++) {
                accO[ni][r * 2]     *= fac;
                accO[ni][r * 2 + 1] *= fac;
            }
        }

        __syncthreads();   // all warps done reading Ks as K
        float* Ps = Ks;    // alias
#pragma unroll
        for (int ni = 0; ni < 8; ni++) {
            Ps[(m0 + g) * 68 + ni * 8 + 2 * t]         = to_tf32(sacc[ni][0]);
            Ps[(m0 + g) * 68 + ni * 8 + 2 * t + 1]     = to_tf32(sacc[ni][1]);
            Ps[(m0 + g + 8) * 68 + ni * 8 + 2 * t]     = to_tf32(sacc[ni][2]);
            Ps[(m0 + g + 8) * 68 + ni * 8 + 2 * t + 1] = to_tf32(sacc[ni][3]);
        }
        __syncwarp();      // warp reads only its own 16 P-rows

        // ---- O += P @ V ----
#pragma unroll
        for (int ks = 0; ks < 8; ks++) {
            unsigned a[4];
            a[0] = __float_as_uint(Ps[(m0 + g) * 68 + ks * 8 + t]);
            a[1] = __float_as_uint(Ps[(m0 + g + 8) * 68 + ks * 8 + t]);
            a[2] = __float_as_uint(Ps[(m0 + g) * 68 + ks * 8 + t + 4]);
            a[3] = __float_as_uint(Ps[(m0 + g + 8) * 68 + ks * 8 + t + 4]);
#pragma unroll
            for (int ni = 0; ni < 8; ni++) {
                unsigned b[2];
                b[0] = __float_as_uint(Vs[(ks * 8 + t) * 68 + ni * 8 + g]);
                b[1] = __float_as_uint(Vs[(ks * 8 + t + 4) * 68 + ni * 8 + g]);
                mma_tf32(accO[ni], a, b);
            }
        }
    }

#pragma unroll
    for (int r = 0; r < 2; r++) {
        float inv = 1.f / lrow[r];
        int row = qt * 64 + m0 + g + r * 8;
#pragma unroll
        for (int ni = 0; ni < 8; ni++) {
            int col = h * 64 + ni * 8 + 2 * t;
            *(float2*)(g_att + (size_t)row * CC + col) =
                make_float2(accO[ni][r * 2] * inv, accO[ni][r * 2 + 1] * inv);
        }
    }
}

// ------------------------------ Router ---------------------------------------
__global__ void zero_counts_kernel() { if (threadIdx.x < EE) g_count[threadIdx.x] = 0; }

__global__ void router_kernel(const float* __restrict__ Wr, const float* __restrict__ br,
                              const float* __restrict__ Wn, const float* __restrict__ bn,
                              const float* __restrict__ noise)
{
    int t = blockIdx.x * 8 + (threadIdx.x >> 5);
    int lane = threadIdx.x & 31;
    const float* xr = g_xn2 + (size_t)t * CC;
    float ar[8] = {0,0,0,0,0,0,0,0}, an[8] = {0,0,0,0,0,0,0,0};
    for (int c = lane; c < CC; c += 32) {
        float xv = xr[c];
        float4 w0 = *(const float4*)(Wr + c * 8);
        float4 w1 = *(const float4*)(Wr + c * 8 + 4);
        ar[0] += xv * w0.x; ar[1] += xv * w0.y; ar[2] += xv * w0.z; ar[3] += xv * w0.w;
        ar[4] += xv * w1.x; ar[5] += xv * w1.y; ar[6] += xv * w1.z; ar[7] += xv * w1.w;
        float4 n0 = *(const float4*)(Wn + c * 8);
        float4 n1 = *(const float4*)(Wn + c * 8 + 4);
        an[0] += xv * n0.x; an[1] += xv * n0.y; an[2] += xv * n0.z; an[3] += xv * n0.w;
        an[4] += xv * n1.x; an[5] += xv * n1.y; an[6] += xv * n1.z; an[7] += xv * n1.w;
    }
#pragma unroll
    for (int e = 0; e < 8; e++) {
#pragma unroll
        for (int o = 16; o > 0; o >>= 1) {
            ar[e] += __shfl_xor_sync(0xffffffffu, ar[e], o);
            an[e] += __shfl_xor_sync(0xffffffffu, an[e], o);
        }
    }
    if (lane == 0) {
        float noisy[8];
#pragma unroll
        for (int e = 0; e < 8; e++) {
            float l  = ar[e] + br[e];
            float nl = an[e] + bn[e];
            float sp = (nl > 20.f) ? nl : log1pf(expf(nl));
            noisy[e] = l + noise[t * 8 + e] * sp;
        }
        int i1 = 0;
        for (int e = 1; e < 8; e++) if (noisy[e] > noisy[i1]) i1 = e;
        int i2 = (i1 == 0) ? 1 : 0;
        for (int e = 0; e < 8; e++)
            if (e != i1 && noisy[e] > noisy[i2]) i2 = e;
        float ee = expf(noisy[i2] - noisy[i1]);
        float z  = 1.f + ee;
        float g1 = 1.f / z, g2 = ee / z;
        int p1 = atomicAdd(&g_count[i1], 1);
        g_list[i1 * TT + p1] = t * 2;     g_gate[t * 2]     = g1;
        int p2 = atomicAdd(&g_count[i2], 1);
        g_list[i2 * TT + p2] = t * 2 + 1; g_gate[t * 2 + 1] = g2;
    }
}

// ------------------------------ Combine --------------------------------------
__global__ void combine_kernel(float* __restrict__ out)
{
    int t = blockIdx.x;
    size_t b0 = (size_t)(t * 2) * CC;
    size_t b1 = (size_t)(t * 2 + 1) * CC;
    for (int c = threadIdx.x; c < CC; c += 256)
        out[(size_t)t * CC + c] += g_O2[b0 + c] + g_O2[b1 + c];
}

// ------------------------------ launch ---------------------------------------
extern "C" void kernel_launch(void* const* d_in, const int* in_sizes, int n_in,
                              void* d_out, int out_size)
{
    (void)in_sizes; (void)n_in; (void)out_size;
    const float* x     = (const float*)d_in[0];
    const float* noise = (const float*)d_in[1];
    const float* ln1_g = (const float*)d_in[2];
    const float* ln1_b = (const float*)d_in[3];
    const float* ln2_g = (const float*)d_in[4];
    const float* ln2_b = (const float*)d_in[5];
    const float* Wq    = (const float*)d_in[6];
    const float* Wk    = (const float*)d_in[7];
    const float* Wv    = (const float*)d_in[8];
    const float* Wproj = (const float*)d_in[9];
    const float* bproj = (const float*)d_in[10];
    const float* Wr    = (const float*)d_in[11];
    const float* br    = (const float*)d_in[12];
    const float* Wn    = (const float*)d_in[13];
    const float* bn    = (const float*)d_in[14];
    const float* W1    = (const float*)d_in[15];
    const float* b1    = (const float*)d_in[16];
    const float* W2    = (const float*)d_in[17];
    const float* b2    = (const float*)d_in[18];
    float* out = (float*)d_out;

    __half *p_hW1, *p_hW2;
    cudaGetSymbolAddress((void**)&p_hW1, h_W1);
    cudaGetSymbolAddress((void**)&p_hW2, h_W2);

    dim3 tb(32, 8);
    transpose_h_kernel<<<dim3(FF / 32, CC / 32, EE), tb>>>(
        W1, p_hW1, CC, FF, (size_t)CC * FF, (size_t)FF * CC);
    transpose_h_kernel<<<dim3(CC / 32, FF / 32, EE), tb>>>(
        W2, p_hW2, FF, CC, (size_t)FF * CC, (size_t)CC * FF);

    ln_kernel<0><<<TT, 256>>>(x, ln1_g, ln1_b);

    gemm_kernel<0><<<dim3(CC / 128, TT / 128, 3), 256>>>(
        Wq, Wk, Wv, nullptr, nullptr, nullptr, CC, CC);

    attn_kernel<<<dim3(TT / 64, HH), 128>>>();

    gemm_kernel<1><<<dim3(CC / 128, TT / 128), 256>>>(
        Wproj, nullptr, nullptr, bproj, x, out, CC, CC);

    ln_kernel<1><<<TT, 256>>>(out, ln2_g, ln2_b);

    zero_counts_kernel<<<1, 32>>>();
    router_kernel<<<TT / 8, 256>>>(Wr, br, Wn, bn, noise);

    gemm_h_kernel<2><<<dim3(FF / 128, 16, EE), 256>>>(b1, CC, FF);
    gemm_h_kernel<3><<<dim3(CC / 128, 16, EE), 256>>>(b2, FF, CC);

    combine_kernel<<<TT, 256>>>(out);
}